// round 1
// baseline (speedup 1.0000x reference)
#include <cuda_runtime.h>
#include <cstddef>

#define T_STEPS 16
#define B_SIZE  16384
#define DIN     64
#define DH      256
#define DMID    64
#define DOUT    4

#define ROWS_PER_CTA 64
#define NTHREADS     256
#define NBLOCKS      (B_SIZE / ROWS_PER_CTA)   // 256

// Padded SMEM strides (conflict-free: stride % 32 == 4 in float units)
#define SH_STRIDE  260   // h tile rows [64][260]
#define SX_STRIDE  68    // x tile rows [64][68]
#define SM_STRIDE  68    // mid tile rows [64][68]
#define WFC_STRIDE 65    // fc weights [4][65]

// SMEM layout (floats)
#define OFF_H     0
#define OFF_X     (OFF_H  + ROWS_PER_CTA * SH_STRIDE)       // 16640
#define OFF_M     (OFF_X  + ROWS_PER_CTA * SX_STRIDE)       // +4352
#define OFF_WFC   (OFF_M  + ROWS_PER_CTA * SM_STRIDE)       // +4352
#define OFF_BH2O  (OFF_WFC + DOUT * WFC_STRIDE)             // +260
#define OFF_BFC   (OFF_BH2O + DMID)
#define OFF_BSUM  (OFF_BFC + DOUT)
#define SMEM_FLOATS (OFF_BSUM + DH)
#define SMEM_BYTES  (SMEM_FLOATS * 4)

// Pre-transposed weights (k-major) — device scratch, no allocation needed.
__device__ float g_Wi2hT[DIN * DH];    // [k][c] k<64,  c<256
__device__ float g_Wh2hT[DH * DH];     // [k][c] k<256, c<256
__device__ float g_Wh2oT[DH * DMID];   // [k][c] k<256, c<64
__device__ float g_bsum[DH];           // b_i2h + b_h2h

__global__ void prep_kernel(const float* __restrict__ Wi2h,
                            const float* __restrict__ bi2h,
                            const float* __restrict__ Wh2h,
                            const float* __restrict__ bh2h,
                            const float* __restrict__ Wh2o) {
    const int stride = gridDim.x * blockDim.x;
    const int tid = blockIdx.x * blockDim.x + threadIdx.x;
    for (int i = tid; i < DH * DH; i += stride) {
        int c = i / DH, k = i % DH;
        g_Wh2hT[k * DH + c] = Wh2h[c * DH + k];
    }
    for (int i = tid; i < DH * DIN; i += stride) {
        int c = i / DIN, k = i % DIN;          // Wi2h is [256][64]
        g_Wi2hT[k * DH + c] = Wi2h[c * DIN + k];
    }
    for (int i = tid; i < DMID * DH; i += stride) {
        int c = i / DH, k = i % DH;            // Wh2o is [64][256]
        g_Wh2oT[k * DMID + c] = Wh2o[c * DH + k];
    }
    for (int i = tid; i < DH; i += stride)
        g_bsum[i] = bi2h[i] + bh2h[i];
}

__global__ void __launch_bounds__(NTHREADS, 2)
rnn_kernel(const float* __restrict__ x,
           const float* __restrict__ hc1,
           const float* __restrict__ Wfc,
           const float* __restrict__ bh2o,
           const float* __restrict__ bfc,
           float* __restrict__ out) {
    extern __shared__ float sm[];
    float* sh    = sm + OFF_H;
    float* sx    = sm + OFF_X;
    float* sms   = sm + OFF_M;
    float* swfc  = sm + OFF_WFC;
    float* sbh2o = sm + OFF_BH2O;
    float* sbfc  = sm + OFF_BFC;
    float* sbsum = sm + OFF_BSUM;

    const int tid = threadIdx.x;
    const int tc = tid & 15;       // column group (16 groups of 16 cols)
    const int tr = tid >> 4;       // row group   (16 groups of 4 rows)
    const int r0 = tr * 4;
    const int c0 = tc * 16;
    const int gbase = blockIdx.x * ROWS_PER_CTA;

    // ---- load constants into SMEM ----
    {
        int c = tid >> 6, k = tid & 63;        // 256 threads cover [4][64]
        swfc[c * WFC_STRIDE + k] = Wfc[c * DMID + k];
        if (tid < DMID) sbh2o[tid] = bh2o[tid];
        if (tid < DOUT) sbfc[tid]  = bfc[tid];
        sbsum[tid] = g_bsum[tid];
    }

    // ---- load initial hidden state ----
    for (int i = tid; i < ROWS_PER_CTA * (DH / 4); i += NTHREADS) {
        int r = i >> 6, q = i & 63;
        float4 v = reinterpret_cast<const float4*>(hc1 + (size_t)(gbase + r) * DH)[q];
        *reinterpret_cast<float4*>(&sh[r * SH_STRIDE + q * 4]) = v;
    }
    __syncthreads();

    float* outseq = out;
    float* hfin   = out + (size_t)T_STEPS * B_SIZE * DOUT;

    for (int t = 0; t < T_STEPS; ++t) {
        // ---- stage x_t tile ----
        const float* xt = x + ((size_t)t * B_SIZE + gbase) * DIN;
        for (int i = tid; i < ROWS_PER_CTA * (DIN / 4); i += NTHREADS) {
            int r = i >> 4, q = i & 15;
            float4 v = reinterpret_cast<const float4*>(xt + (size_t)r * DIN)[q];
            *reinterpret_cast<float4*>(&sx[r * SX_STRIDE + q * 4]) = v;
        }
        __syncthreads();

        // ---- GEMM1: pre = x@Wi2h^T + h@Wh2h^T + bsum ; h_new = tanh(pre) ----
        float acc[4][16];
        #pragma unroll
        for (int j = 0; j < 16; ++j) {
            float b = sbsum[c0 + j];
            acc[0][j] = b; acc[1][j] = b; acc[2][j] = b; acc[3][j] = b;
        }

        // phase A: K=64, A = sx
        #pragma unroll 2
        for (int k = 0; k < DIN; k += 4) {
            float4 av[4];
            #pragma unroll
            for (int i = 0; i < 4; ++i)
                av[i] = *reinterpret_cast<const float4*>(&sx[(r0 + i) * SX_STRIDE + k]);
            #pragma unroll
            for (int kk = 0; kk < 4; ++kk) {
                const float4* wp = reinterpret_cast<const float4*>(g_Wi2hT + (size_t)(k + kk) * DH + c0);
                float4 w0 = wp[0], w1 = wp[1], w2 = wp[2], w3 = wp[3];
                #pragma unroll
                for (int i = 0; i < 4; ++i) {
                    float a = reinterpret_cast<const float*>(&av[i])[kk];
                    acc[i][0]  += a * w0.x; acc[i][1]  += a * w0.y;
                    acc[i][2]  += a * w0.z; acc[i][3]  += a * w0.w;
                    acc[i][4]  += a * w1.x; acc[i][5]  += a * w1.y;
                    acc[i][6]  += a * w1.z; acc[i][7]  += a * w1.w;
                    acc[i][8]  += a * w2.x; acc[i][9]  += a * w2.y;
                    acc[i][10] += a * w2.z; acc[i][11] += a * w2.w;
                    acc[i][12] += a * w3.x; acc[i][13] += a * w3.y;
                    acc[i][14] += a * w3.z; acc[i][15] += a * w3.w;
                }
            }
        }

        // phase B: K=256, A = sh (h_old)
        #pragma unroll 2
        for (int k = 0; k < DH; k += 4) {
            float4 av[4];
            #pragma unroll
            for (int i = 0; i < 4; ++i)
                av[i] = *reinterpret_cast<const float4*>(&sh[(r0 + i) * SH_STRIDE + k]);
            #pragma unroll
            for (int kk = 0; kk < 4; ++kk) {
                const float4* wp = reinterpret_cast<const float4*>(g_Wh2hT + (size_t)(k + kk) * DH + c0);
                float4 w0 = wp[0], w1 = wp[1], w2 = wp[2], w3 = wp[3];
                #pragma unroll
                for (int i = 0; i < 4; ++i) {
                    float a = reinterpret_cast<const float*>(&av[i])[kk];
                    acc[i][0]  += a * w0.x; acc[i][1]  += a * w0.y;
                    acc[i][2]  += a * w0.z; acc[i][3]  += a * w0.w;
                    acc[i][4]  += a * w1.x; acc[i][5]  += a * w1.y;
                    acc[i][6]  += a * w1.z; acc[i][7]  += a * w1.w;
                    acc[i][8]  += a * w2.x; acc[i][9]  += a * w2.y;
                    acc[i][10] += a * w2.z; acc[i][11] += a * w2.w;
                    acc[i][12] += a * w3.x; acc[i][13] += a * w3.y;
                    acc[i][14] += a * w3.z; acc[i][15] += a * w3.w;
                }
            }
        }

        #pragma unroll
        for (int i = 0; i < 4; ++i)
            #pragma unroll
            for (int j = 0; j < 16; ++j)
                acc[i][j] = tanhf(acc[i][j]);

        __syncthreads();   // all reads of h_old complete before overwrite
        #pragma unroll
        for (int i = 0; i < 4; ++i) {
            float* dst = &sh[(r0 + i) * SH_STRIDE + c0];
            #pragma unroll
            for (int j4 = 0; j4 < 4; ++j4) {
                float4 v = make_float4(acc[i][j4 * 4 + 0], acc[i][j4 * 4 + 1],
                                       acc[i][j4 * 4 + 2], acc[i][j4 * 4 + 3]);
                *reinterpret_cast<float4*>(dst + j4 * 4) = v;
            }
        }
        __syncthreads();

        // ---- GEMM2: mid = tanh(h_new @ Wh2o^T + b_h2o), tile 64x64, 4x4/thread ----
        const int cm0 = tc * 4;
        float acc2[4][4];
        #pragma unroll
        for (int j = 0; j < 4; ++j) {
            float b = sbh2o[cm0 + j];
            acc2[0][j] = b; acc2[1][j] = b; acc2[2][j] = b; acc2[3][j] = b;
        }
        #pragma unroll 2
        for (int k = 0; k < DH; k += 4) {
            float4 av[4];
            #pragma unroll
            for (int i = 0; i < 4; ++i)
                av[i] = *reinterpret_cast<const float4*>(&sh[(r0 + i) * SH_STRIDE + k]);
            #pragma unroll
            for (int kk = 0; kk < 4; ++kk) {
                float4 w = *reinterpret_cast<const float4*>(g_Wh2oT + (size_t)(k + kk) * DMID + cm0);
                #pragma unroll
                for (int i = 0; i < 4; ++i) {
                    float a = reinterpret_cast<const float*>(&av[i])[kk];
                    acc2[i][0] += a * w.x; acc2[i][1] += a * w.y;
                    acc2[i][2] += a * w.z; acc2[i][3] += a * w.w;
                }
            }
        }
        #pragma unroll
        for (int i = 0; i < 4; ++i) {
            float* dst = &sms[(r0 + i) * SM_STRIDE + cm0];
            dst[0] = tanhf(acc2[i][0]); dst[1] = tanhf(acc2[i][1]);
            dst[2] = tanhf(acc2[i][2]); dst[3] = tanhf(acc2[i][3]);
        }
        __syncthreads();

        // ---- GEMM3: out = mid @ Wfc^T + b_fc, one output/thread ----
        {
            const int row = tid >> 2;
            const int col = tid & 3;
            float a3 = sbfc[col];
            const float* mrow = &sms[row * SM_STRIDE];
            const float* wrow = &swfc[col * WFC_STRIDE];
            #pragma unroll 8
            for (int k = 0; k < DMID; ++k)
                a3 = fmaf(mrow[k], wrow[k], a3);
            outseq[((size_t)t * B_SIZE + gbase + row) * DOUT + col] = a3;
        }
        __syncthreads();
    }

    // ---- write h_final ----
    for (int i = tid; i < ROWS_PER_CTA * (DH / 4); i += NTHREADS) {
        int r = i >> 6, q = i & 63;
        float4 v = *reinterpret_cast<const float4*>(&sh[r * SH_STRIDE + q * 4]);
        reinterpret_cast<float4*>(hfin + (size_t)(gbase + r) * DH)[q] = v;
    }
}

extern "C" void kernel_launch(void* const* d_in, const int* in_sizes, int n_in,
                              void* d_out, int out_size) {
    const float* x    = (const float*)d_in[0];
    const float* hc1  = (const float*)d_in[1];
    const float* Wi2h = (const float*)d_in[2];
    const float* bi2h = (const float*)d_in[3];
    const float* Wh2h = (const float*)d_in[4];
    const float* bh2h = (const float*)d_in[5];
    const float* Wh2o = (const float*)d_in[6];
    const float* bh2o = (const float*)d_in[7];
    const float* Wfc  = (const float*)d_in[8];
    const float* bfc  = (const float*)d_in[9];
    float* out = (float*)d_out;

    cudaFuncSetAttribute(rnn_kernel, cudaFuncAttributeMaxDynamicSharedMemorySize, SMEM_BYTES);

    prep_kernel<<<64, 256>>>(Wi2h, bi2h, Wh2h, bh2h, Wh2o);
    rnn_kernel<<<NBLOCKS, NTHREADS, SMEM_BYTES>>>(x, hc1, Wfc, bh2o, bfc, out);
}

// round 2
// speedup vs baseline: 1.9497x; 1.9497x over previous
#include <cuda_runtime.h>
#include <cstddef>

#define T_STEPS 16
#define B_SIZE  16384
#define DIN     64
#define DH      256
#define DMID    64
#define DOUT    4
#define KTOT    (DIN + DH)      // 320 combined K for GEMM1

#define ROWS_PER_CTA 64
#define NTHREADS     256
#define NBLOCKS      (B_SIZE / ROWS_PER_CTA)   // 256

#define AT_STRIDE 68            // shAT row stride (floats): 64 rows + 4 gap
#define SM_STRIDE 68
#define WFC_STRIDE 65

// row -> in-row offset with 16B gap after row 31 (conflict-free 8-group LDS)
#define ROFF(r) ((r) + ((((r) >> 5)) << 2))

// SMEM layout (floats)
#define OFF_AT    0
#define OFF_M     (OFF_AT + KTOT * AT_STRIDE)            // 21760
#define OFF_WFC   (OFF_M + ROWS_PER_CTA * SM_STRIDE)     // +4352
#define OFF_BH2O  (OFF_WFC + DOUT * WFC_STRIDE)
#define OFF_BFC   (OFF_BH2O + DMID)
#define OFF_BSUM  (OFF_BFC + DOUT)
#define SMEM_FLOATS (OFF_BSUM + DH)
#define SMEM_BYTES  (SMEM_FLOATS * 4)

// Device scratch: combined k-major weights
__device__ float g_Wcomb[KTOT * DH];    // [k][c] k<320, c<256 (rows 0..63 = Wi2h^T, 64..319 = Wh2h^T)
__device__ float g_Wh2oT[DH * DMID];    // [k][c] k<256, c<64
__device__ float g_bsum[DH];

__global__ void prep_kernel(const float* __restrict__ Wi2h,
                            const float* __restrict__ bi2h,
                            const float* __restrict__ Wh2h,
                            const float* __restrict__ bh2h,
                            const float* __restrict__ Wh2o) {
    const int stride = gridDim.x * blockDim.x;
    const int tid = blockIdx.x * blockDim.x + threadIdx.x;
    for (int i = tid; i < DH * DIN; i += stride) {        // Wi2h [256][64]
        int c = i / DIN, k = i % DIN;
        g_Wcomb[k * DH + c] = Wi2h[i];
    }
    for (int i = tid; i < DH * DH; i += stride) {         // Wh2h [256][256]
        int c = i / DH, k = i % DH;
        g_Wcomb[(DIN + k) * DH + c] = Wh2h[i];
    }
    for (int i = tid; i < DMID * DH; i += stride) {       // Wh2o [64][256]
        int c = i / DH, k = i % DH;
        g_Wh2oT[k * DMID + c] = Wh2o[i];
    }
    for (int i = tid; i < DH; i += stride)
        g_bsum[i] = bi2h[i] + bh2h[i];
}

__global__ void __launch_bounds__(NTHREADS, 2)
rnn_kernel(const float* __restrict__ x,
           const float* __restrict__ hc1,
           const float* __restrict__ Wfc,
           const float* __restrict__ bh2o,
           const float* __restrict__ bfc,
           float* __restrict__ out) {
    extern __shared__ float sm[];
    float* shAT  = sm + OFF_AT;
    float* sms   = sm + OFF_M;
    float* swfc  = sm + OFF_WFC;
    float* sbh2o = sm + OFF_BH2O;
    float* sbfc  = sm + OFF_BFC;
    float* sbsum = sm + OFF_BSUM;

    const int tid  = threadIdx.x;
    const int w    = tid >> 5;          // warp 0..7
    const int lane = tid & 31;
    const int g    = lane >> 2;         // row group 0..7 (rows g*8..g*8+7)
    const int aoff = ROFF(g * 8);       // in-row float offset for this thread's 8 rows
    const int cbase = w * 32 + (lane & 3) * 8;   // 8 contiguous cols for GEMM1
    const int cb2   = w * 8  + (lane & 3) * 2;   // 2 cols for GEMM2
    const int gbase = blockIdx.x * ROWS_PER_CTA;

    // ---- constants ----
    {
        int c = tid >> 6, k = tid & 63;
        swfc[c * WFC_STRIDE + k] = Wfc[c * DMID + k];
        if (tid < DMID) sbh2o[tid] = bh2o[tid];
        if (tid < DOUT) sbfc[tid]  = bfc[tid];
        sbsum[tid] = g_bsum[tid];
    }

    // ---- stage hc1^T into shAT rows 64..319 ----
    for (int idx = tid; idx < ROWS_PER_CTA * (DH / 4); idx += NTHREADS) {
        int r = idx & 63, q = idx >> 6;     // q 0..63
        float4 v = *reinterpret_cast<const float4*>(hc1 + (size_t)(gbase + r) * DH + q * 4);
        int ro = ROFF(r);
        shAT[(DIN + q * 4 + 0) * AT_STRIDE + ro] = v.x;
        shAT[(DIN + q * 4 + 1) * AT_STRIDE + ro] = v.y;
        shAT[(DIN + q * 4 + 2) * AT_STRIDE + ro] = v.z;
        shAT[(DIN + q * 4 + 3) * AT_STRIDE + ro] = v.w;
    }
    __syncthreads();

    float* outseq = out;
    float* hfin   = out + (size_t)T_STEPS * B_SIZE * DOUT;

    for (int t = 0; t < T_STEPS; ++t) {
        // ---- stage x_t^T into shAT rows 0..63 (overlaps prev GEMM2/3) ----
        const float* xt = x + ((size_t)t * B_SIZE + gbase) * DIN;
        for (int idx = tid; idx < ROWS_PER_CTA * (DIN / 4); idx += NTHREADS) {
            int r = idx & 63, q = idx >> 6;  // q 0..15
            float4 v = *reinterpret_cast<const float4*>(xt + (size_t)r * DIN + q * 4);
            int ro = ROFF(r);
            shAT[(q * 4 + 0) * AT_STRIDE + ro] = v.x;
            shAT[(q * 4 + 1) * AT_STRIDE + ro] = v.y;
            shAT[(q * 4 + 2) * AT_STRIDE + ro] = v.z;
            shAT[(q * 4 + 3) * AT_STRIDE + ro] = v.w;
        }
        __syncthreads();   // [A] x staged; prev step fully done

        // ---- GEMM1: [64 x 320] x [320 x 256], thread = 8 rows x 8 cols ----
        float acc[8][8];
        #pragma unroll
        for (int j = 0; j < 8; ++j) {
            float b = sbsum[cbase + j];
            #pragma unroll
            for (int i = 0; i < 8; ++i) acc[i][j] = b;
        }

        {
            const float* Wp = g_Wcomb + cbase;
            const float* Ap = shAT + aoff;
            #pragma unroll 2
            for (int k = 0; k < KTOT; ++k) {
                float4 a0 = *reinterpret_cast<const float4*>(Ap + k * AT_STRIDE);
                float4 a1 = *reinterpret_cast<const float4*>(Ap + k * AT_STRIDE + 4);
                float4 w0 = __ldg(reinterpret_cast<const float4*>(Wp + (size_t)k * DH));
                float4 w1 = __ldg(reinterpret_cast<const float4*>(Wp + (size_t)k * DH + 4));
                float av[8] = {a0.x, a0.y, a0.z, a0.w, a1.x, a1.y, a1.z, a1.w};
                float wv[8] = {w0.x, w0.y, w0.z, w0.w, w1.x, w1.y, w1.z, w1.w};
                #pragma unroll
                for (int i = 0; i < 8; ++i)
                    #pragma unroll
                    for (int j = 0; j < 8; ++j)
                        acc[i][j] = fmaf(av[i], wv[j], acc[i][j]);
            }
        }

        #pragma unroll
        for (int i = 0; i < 8; ++i)
            #pragma unroll
            for (int j = 0; j < 8; ++j)
                acc[i][j] = tanhf(acc[i][j]);

        __syncthreads();   // [B] all shAT reads of step t done

        // write h_new^T back into shAT rows 64..319 (exactly GEMM2's A layout)
        #pragma unroll
        for (int j = 0; j < 8; ++j) {
            int c = cbase + j;
            float4 lo = make_float4(acc[0][j], acc[1][j], acc[2][j], acc[3][j]);
            float4 hi = make_float4(acc[4][j], acc[5][j], acc[6][j], acc[7][j]);
            *reinterpret_cast<float4*>(&shAT[(DIN + c) * AT_STRIDE + aoff])     = lo;
            *reinterpret_cast<float4*>(&shAT[(DIN + c) * AT_STRIDE + aoff + 4]) = hi;
        }
        __syncthreads();   // [C] h_new^T visible

        // ---- GEMM2: [64 x 256] x [256 x 64], thread = 8 rows x 2 cols ----
        float acc2[8][2];
        {
            float b0 = sbh2o[cb2], b1 = sbh2o[cb2 + 1];
            #pragma unroll
            for (int i = 0; i < 8; ++i) { acc2[i][0] = b0; acc2[i][1] = b1; }
        }
        {
            const float* Ap = shAT + (size_t)DIN * AT_STRIDE + aoff;
            const float* Wp = g_Wh2oT + cb2;
            #pragma unroll 4
            for (int k = 0; k < DH; ++k) {
                float4 a0 = *reinterpret_cast<const float4*>(Ap + k * AT_STRIDE);
                float4 a1 = *reinterpret_cast<const float4*>(Ap + k * AT_STRIDE + 4);
                float2 wv = __ldg(reinterpret_cast<const float2*>(Wp + (size_t)k * DMID));
                float av[8] = {a0.x, a0.y, a0.z, a0.w, a1.x, a1.y, a1.z, a1.w};
                #pragma unroll
                for (int i = 0; i < 8; ++i) {
                    acc2[i][0] = fmaf(av[i], wv.x, acc2[i][0]);
                    acc2[i][1] = fmaf(av[i], wv.y, acc2[i][1]);
                }
            }
        }
        {
            int rg = g * 8;
            #pragma unroll
            for (int i = 0; i < 8; ++i) {
                sms[(rg + i) * SM_STRIDE + cb2]     = tanhf(acc2[i][0]);
                sms[(rg + i) * SM_STRIDE + cb2 + 1] = tanhf(acc2[i][1]);
            }
        }
        __syncthreads();   // [D] mid ready

        // ---- GEMM3: [64 x 64] x [64 x 4], one output per thread ----
        {
            const int row = tid >> 2;
            const int col = tid & 3;
            float a3 = sbfc[col];
            const float* mrow = &sms[row * SM_STRIDE];
            const float* wrow = &swfc[col * WFC_STRIDE];
            #pragma unroll 8
            for (int k = 0; k < DMID; ++k)
                a3 = fmaf(mrow[k], wrow[k], a3);
            outseq[((size_t)t * B_SIZE + gbase + row) * DOUT + col] = a3;
        }
        // no barrier: next x-stage writes shAT rows<64; GEMM3 reads sms only,
        // protected by [A] of next iteration before GEMM1, and sms rewritten
        // only after [C] of next iteration.
    }

    __syncthreads();
    // ---- h_final from shAT rows 64..319 ----
    for (int idx = tid; idx < ROWS_PER_CTA * (DH / 4); idx += NTHREADS) {
        int r = idx & 63, q = idx >> 6;
        int ro = ROFF(r);
        float4 v;
        v.x = shAT[(DIN + q * 4 + 0) * AT_STRIDE + ro];
        v.y = shAT[(DIN + q * 4 + 1) * AT_STRIDE + ro];
        v.z = shAT[(DIN + q * 4 + 2) * AT_STRIDE + ro];
        v.w = shAT[(DIN + q * 4 + 3) * AT_STRIDE + ro];
        *reinterpret_cast<float4*>(hfin + (size_t)(gbase + r) * DH + q * 4) = v;
    }
}

extern "C" void kernel_launch(void* const* d_in, const int* in_sizes, int n_in,
                              void* d_out, int out_size) {
    const float* x    = (const float*)d_in[0];
    const float* hc1  = (const float*)d_in[1];
    const float* Wi2h = (const float*)d_in[2];
    const float* bi2h = (const float*)d_in[3];
    const float* Wh2h = (const float*)d_in[4];
    const float* bh2h = (const float*)d_in[5];
    const float* Wh2o = (const float*)d_in[6];
    const float* bh2o = (const float*)d_in[7];
    const float* Wfc  = (const float*)d_in[8];
    const float* bfc  = (const float*)d_in[9];
    float* out = (float*)d_out;

    cudaFuncSetAttribute(rnn_kernel, cudaFuncAttributeMaxDynamicSharedMemorySize, SMEM_BYTES);

    prep_kernel<<<64, 256>>>(Wi2h, bi2h, Wh2h, bh2h, Wh2o);
    rnn_kernel<<<NBLOCKS, NTHREADS, SMEM_BYTES>>>(x, hc1, Wfc, bh2o, bfc, out);
}

// round 3
// speedup vs baseline: 2.4301x; 1.2464x over previous
#include <cuda_runtime.h>
#include <cstddef>

#define T_STEPS 16
#define B_SIZE  16384
#define DIN     64
#define DH      256
#define DMID    64
#define DOUT    4
#define KTOT    (DIN + DH)      // 320 combined K for GEMM1

#define ROWS_PER_CTA 64
#define NTHREADS     256
#define NBLOCKS      (B_SIZE / ROWS_PER_CTA)   // 256

#define AT_STRIDE 68
#define SM_STRIDE 68
#define WFC_STRIDE 65

// row -> in-row offset with 16B gap after row 31 (conflict-free 8-group LDS)
#define ROFF(r) ((r) + ((((r) >> 5)) << 2))

// SMEM layout (floats)
#define OFF_AT    0
#define OFF_M     (OFF_AT + KTOT * AT_STRIDE)
#define OFF_WFC   (OFF_M + ROWS_PER_CTA * SM_STRIDE)
#define OFF_BH2O  (OFF_WFC + DOUT * WFC_STRIDE)
#define OFF_BFC   (OFF_BH2O + DMID)
#define OFF_BSUM  (OFF_BFC + DOUT)
#define SMEM_FLOATS (OFF_BSUM + DH)
#define SMEM_BYTES  (SMEM_FLOATS * 4)

// Device scratch (padded +4 rows for harmless OOB prefetch)
__device__ float g_Wcomb[(KTOT + 4) * DH];
__device__ float g_Wh2oT[(DH + 4) * DMID];
__device__ float g_bsum[DH];

// ---- packed f32x2 helpers (sm_103a FFMA2) ----
__device__ __forceinline__ unsigned long long packf2(float f) {
    unsigned long long d;
    asm("mov.b64 %0, {%1, %1};" : "=l"(d) : "f"(f));
    return d;
}
__device__ __forceinline__ void ffma2(unsigned long long& c,
                                      unsigned long long a,
                                      unsigned long long b) {
    asm("fma.rn.f32x2 %0, %1, %2, %0;" : "+l"(c) : "l"(a), "l"(b));
}
__device__ __forceinline__ float2 unpackf2(unsigned long long p) {
    float2 r;
    asm("mov.b64 {%0, %1}, %2;" : "=f"(r.x), "=f"(r.y) : "l"(p));
    return r;
}

__global__ void prep_kernel(const float* __restrict__ Wi2h,
                            const float* __restrict__ bi2h,
                            const float* __restrict__ Wh2h,
                            const float* __restrict__ bh2h,
                            const float* __restrict__ Wh2o) {
    const int stride = gridDim.x * blockDim.x;
    const int tid = blockIdx.x * blockDim.x + threadIdx.x;
    for (int i = tid; i < DH * DIN; i += stride) {        // Wi2h [256][64]
        int c = i / DIN, k = i % DIN;
        g_Wcomb[k * DH + c] = Wi2h[i];
    }
    for (int i = tid; i < DH * DH; i += stride) {         // Wh2h [256][256]
        int c = i / DH, k = i % DH;
        g_Wcomb[(DIN + k) * DH + c] = Wh2h[i];
    }
    for (int i = tid; i < DMID * DH; i += stride) {       // Wh2o [64][256]
        int c = i / DH, k = i % DH;
        g_Wh2oT[k * DMID + c] = Wh2o[i];
    }
    for (int i = tid; i < DH; i += stride)
        g_bsum[i] = bi2h[i] + bh2h[i];
}

// A-tile load: 8 rows at column k -> 4 packed row-pairs
#define LDA1(dst, k) do {                                                          \
    ulonglong2 q0 = *reinterpret_cast<const ulonglong2*>(Ap + (k) * AT_STRIDE);    \
    ulonglong2 q1 = *reinterpret_cast<const ulonglong2*>(Ap + (k) * AT_STRIDE + 4);\
    dst[0] = q0.x; dst[1] = q0.y; dst[2] = q1.x; dst[3] = q1.y; } while (0)

#define LDW1(w0, w1, k) do {                                                       \
    w0 = __ldg(reinterpret_cast<const float4*>(Wp + (size_t)(k) * DH));            \
    w1 = __ldg(reinterpret_cast<const float4*>(Wp + (size_t)(k) * DH + 4)); } while (0)

#define COMP1(ap, w0, w1) do {                                                     \
    unsigned long long wq[8];                                                      \
    wq[0] = packf2(w0.x); wq[1] = packf2(w0.y);                                    \
    wq[2] = packf2(w0.z); wq[3] = packf2(w0.w);                                    \
    wq[4] = packf2(w1.x); wq[5] = packf2(w1.y);                                    \
    wq[6] = packf2(w1.z); wq[7] = packf2(w1.w);                                    \
    _Pragma("unroll")                                                              \
    for (int ip_ = 0; ip_ < 4; ++ip_)                                              \
        _Pragma("unroll")                                                          \
        for (int j_ = 0; j_ < 8; ++j_)                                             \
            ffma2(acc[ip_][j_], ap[ip_], wq[j_]); } while (0)

#define LDA2(dst, k) do {                                                          \
    ulonglong2 q0 = *reinterpret_cast<const ulonglong2*>(Ap2 + (k) * AT_STRIDE);   \
    ulonglong2 q1 = *reinterpret_cast<const ulonglong2*>(Ap2 + (k) * AT_STRIDE + 4);\
    dst[0] = q0.x; dst[1] = q0.y; dst[2] = q1.x; dst[3] = q1.y; } while (0)

#define COMP2(ap, w) do {                                                          \
    unsigned long long wq0 = packf2(w.x), wq1 = packf2(w.y);                       \
    _Pragma("unroll")                                                              \
    for (int ip_ = 0; ip_ < 4; ++ip_) {                                            \
        ffma2(acc2[ip_][0], ap[ip_], wq0);                                         \
        ffma2(acc2[ip_][1], ap[ip_], wq1); } } while (0)

__global__ void __launch_bounds__(NTHREADS, 2)
rnn_kernel(const float* __restrict__ x,
           const float* __restrict__ hc1,
           const float* __restrict__ Wfc,
           const float* __restrict__ bh2o,
           const float* __restrict__ bfc,
           float* __restrict__ out) {
    extern __shared__ float sm[];
    float* shAT  = sm + OFF_AT;
    float* sms   = sm + OFF_M;
    float* swfc  = sm + OFF_WFC;
    float* sbh2o = sm + OFF_BH2O;
    float* sbfc  = sm + OFF_BFC;
    float* sbsum = sm + OFF_BSUM;

    const int tid  = threadIdx.x;
    const int w    = tid >> 5;
    const int lane = tid & 31;
    const int g    = lane >> 2;
    const int aoff = ROFF(g * 8);
    const int cbase = w * 32 + (lane & 3) * 8;
    const int cb2   = w * 8  + (lane & 3) * 2;
    const int gbase = blockIdx.x * ROWS_PER_CTA;

    {
        int c = tid >> 6, k = tid & 63;
        swfc[c * WFC_STRIDE + k] = Wfc[c * DMID + k];
        if (tid < DMID) sbh2o[tid] = bh2o[tid];
        if (tid < DOUT) sbfc[tid]  = bfc[tid];
        sbsum[tid] = g_bsum[tid];
    }

    for (int idx = tid; idx < ROWS_PER_CTA * (DH / 4); idx += NTHREADS) {
        int r = idx & 63, q = idx >> 6;
        float4 v = *reinterpret_cast<const float4*>(hc1 + (size_t)(gbase + r) * DH + q * 4);
        int ro = ROFF(r);
        shAT[(DIN + q * 4 + 0) * AT_STRIDE + ro] = v.x;
        shAT[(DIN + q * 4 + 1) * AT_STRIDE + ro] = v.y;
        shAT[(DIN + q * 4 + 2) * AT_STRIDE + ro] = v.z;
        shAT[(DIN + q * 4 + 3) * AT_STRIDE + ro] = v.w;
    }
    __syncthreads();

    float* outseq = out;
    float* hfin   = out + (size_t)T_STEPS * B_SIZE * DOUT;

    for (int t = 0; t < T_STEPS; ++t) {
        // ---- stage x_t^T ----
        const float* xt = x + ((size_t)t * B_SIZE + gbase) * DIN;
        for (int idx = tid; idx < ROWS_PER_CTA * (DIN / 4); idx += NTHREADS) {
            int r = idx & 63, q = idx >> 6;
            float4 v = *reinterpret_cast<const float4*>(xt + (size_t)r * DIN + q * 4);
            int ro = ROFF(r);
            shAT[(q * 4 + 0) * AT_STRIDE + ro] = v.x;
            shAT[(q * 4 + 1) * AT_STRIDE + ro] = v.y;
            shAT[(q * 4 + 2) * AT_STRIDE + ro] = v.z;
            shAT[(q * 4 + 3) * AT_STRIDE + ro] = v.w;
        }
        __syncthreads();   // [A]

        // ---- GEMM1: packed row-pair accumulators, 4-stage pipelined k loop ----
        unsigned long long acc[4][8];
        #pragma unroll
        for (int j = 0; j < 8; ++j) {
            unsigned long long b = packf2(sbsum[cbase + j]);
            acc[0][j] = b; acc[1][j] = b; acc[2][j] = b; acc[3][j] = b;
        }

        {
            const float* Ap = shAT + aoff;
            const float* Wp = g_Wcomb + cbase;
            unsigned long long A0[4], A1[4];
            float4 wa0, wa1, wb0, wb1, wc0, wc1, wd0, wd1;
            LDA1(A0, 0);
            LDW1(wa0, wa1, 0);
            LDW1(wb0, wb1, 1);
            #pragma unroll 1
            for (int k = 0; k < KTOT; k += 4) {
                LDA1(A1, k + 1);
                LDW1(wc0, wc1, k + 2);
                LDW1(wd0, wd1, k + 3);
                COMP1(A0, wa0, wa1);
                LDA1(A0, k + 2);
                COMP1(A1, wb0, wb1);
                LDA1(A1, k + 3);
                LDW1(wa0, wa1, k + 4);
                LDW1(wb0, wb1, k + 5);
                COMP1(A0, wc0, wc1);
                LDA1(A0, k + 4);
                COMP1(A1, wd0, wd1);
            }
        }

        // unpack + tanh
        float accf[8][8];
        #pragma unroll
        for (int ip = 0; ip < 4; ++ip)
            #pragma unroll
            for (int j = 0; j < 8; ++j) {
                float2 v = unpackf2(acc[ip][j]);
                accf[2 * ip + 0][j] = tanhf(v.x);
                accf[2 * ip + 1][j] = tanhf(v.y);
            }

        __syncthreads();   // [B]

        #pragma unroll
        for (int j = 0; j < 8; ++j) {
            int c = cbase + j;
            float4 lo = make_float4(accf[0][j], accf[1][j], accf[2][j], accf[3][j]);
            float4 hi = make_float4(accf[4][j], accf[5][j], accf[6][j], accf[7][j]);
            *reinterpret_cast<float4*>(&shAT[(DIN + c) * AT_STRIDE + aoff])     = lo;
            *reinterpret_cast<float4*>(&shAT[(DIN + c) * AT_STRIDE + aoff + 4]) = hi;
        }
        __syncthreads();   // [C]

        // ---- GEMM2: [64x256]x[256x64], packed pairs, pipelined ----
        unsigned long long acc2[4][2];
        {
            unsigned long long b0 = packf2(sbh2o[cb2]);
            unsigned long long b1 = packf2(sbh2o[cb2 + 1]);
            #pragma unroll
            for (int ip = 0; ip < 4; ++ip) { acc2[ip][0] = b0; acc2[ip][1] = b1; }
        }
        {
            const float* Ap2 = shAT + (size_t)DIN * AT_STRIDE + aoff;
            const float* Wp2 = g_Wh2oT + cb2;
            unsigned long long A0[4], A1[4];
            float2 wa, wb, wc, wd;
            LDA2(A0, 0);
            wa = __ldg(reinterpret_cast<const float2*>(Wp2));
            wb = __ldg(reinterpret_cast<const float2*>(Wp2 + DMID));
            #pragma unroll 1
            for (int k = 0; k < DH; k += 4) {
                LDA2(A1, k + 1);
                wc = __ldg(reinterpret_cast<const float2*>(Wp2 + (size_t)(k + 2) * DMID));
                wd = __ldg(reinterpret_cast<const float2*>(Wp2 + (size_t)(k + 3) * DMID));
                COMP2(A0, wa);
                LDA2(A0, k + 2);
                COMP2(A1, wb);
                LDA2(A1, k + 3);
                wa = __ldg(reinterpret_cast<const float2*>(Wp2 + (size_t)(k + 4) * DMID));
                wb = __ldg(reinterpret_cast<const float2*>(Wp2 + (size_t)(k + 5) * DMID));
                COMP2(A0, wc);
                LDA2(A0, k + 4);
                COMP2(A1, wd);
            }
        }
        {
            int rg = g * 8;
            #pragma unroll
            for (int ip = 0; ip < 4; ++ip) {
                float2 v0 = unpackf2(acc2[ip][0]);
                float2 v1 = unpackf2(acc2[ip][1]);
                sms[(rg + 2 * ip + 0) * SM_STRIDE + cb2]     = tanhf(v0.x);
                sms[(rg + 2 * ip + 1) * SM_STRIDE + cb2]     = tanhf(v0.y);
                sms[(rg + 2 * ip + 0) * SM_STRIDE + cb2 + 1] = tanhf(v1.x);
                sms[(rg + 2 * ip + 1) * SM_STRIDE + cb2 + 1] = tanhf(v1.y);
            }
        }
        __syncthreads();   // [D]

        // ---- GEMM3 ----
        {
            const int row = tid >> 2;
            const int col = tid & 3;
            float a3 = sbfc[col];
            const float* mrow = &sms[row * SM_STRIDE];
            const float* wrow = &swfc[col * WFC_STRIDE];
            #pragma unroll 8
            for (int k = 0; k < DMID; ++k)
                a3 = fmaf(mrow[k], wrow[k], a3);
            outseq[((size_t)t * B_SIZE + gbase + row) * DOUT + col] = a3;
        }
    }

    __syncthreads();
    for (int idx = tid; idx < ROWS_PER_CTA * (DH / 4); idx += NTHREADS) {
        int r = idx & 63, q = idx >> 6;
        int ro = ROFF(r);
        float4 v;
        v.x = shAT[(DIN + q * 4 + 0) * AT_STRIDE + ro];
        v.y = shAT[(DIN + q * 4 + 1) * AT_STRIDE + ro];
        v.z = shAT[(DIN + q * 4 + 2) * AT_STRIDE + ro];
        v.w = shAT[(DIN + q * 4 + 3) * AT_STRIDE + ro];
        *reinterpret_cast<float4*>(hfin + (size_t)(gbase + r) * DH + q * 4) = v;
    }
}

extern "C" void kernel_launch(void* const* d_in, const int* in_sizes, int n_in,
                              void* d_out, int out_size) {
    const float* x    = (const float*)d_in[0];
    const float* hc1  = (const float*)d_in[1];
    const float* Wi2h = (const float*)d_in[2];
    const float* bi2h = (const float*)d_in[3];
    const float* Wh2h = (const float*)d_in[4];
    const float* bh2h = (const float*)d_in[5];
    const float* Wh2o = (const float*)d_in[6];
    const float* bh2o = (const float*)d_in[7];
    const float* Wfc  = (const float*)d_in[8];
    const float* bfc  = (const float*)d_in[9];
    float* out = (float*)d_out;

    cudaFuncSetAttribute(rnn_kernel, cudaFuncAttributeMaxDynamicSharedMemorySize, SMEM_BYTES);

    prep_kernel<<<64, 256>>>(Wi2h, bi2h, Wh2h, bh2h, Wh2o);
    rnn_kernel<<<NBLOCKS, NTHREADS, SMEM_BYTES>>>(x, hc1, Wfc, bh2o, bfc, out);
}

// round 4
// speedup vs baseline: 2.4305x; 1.0002x over previous
#include <cuda_runtime.h>
#include <cstddef>

#define T_STEPS 16
#define B_SIZE  16384
#define DIN     64
#define DH      256
#define DMID    64
#define DOUT    4
#define KTOT    (DIN + DH)      // 320 combined K for GEMM1

#define ROWS_PER_CTA 64
#define NTHREADS     256
#define NBLOCKS      (B_SIZE / ROWS_PER_CTA)   // 256

#define AT_STRIDE 68
#define SM_STRIDE 68
#define WFC_STRIDE 65

// row -> in-row offset with 16B gap after row 31 (conflict-free 8-group LDS)
#define ROFF(r) ((r) + ((((r) >> 5)) << 2))

// SMEM layout (floats)
#define OFF_AT    0
#define OFF_M     (OFF_AT + KTOT * AT_STRIDE)
#define OFF_WFC   (OFF_M + ROWS_PER_CTA * SM_STRIDE)
#define OFF_BH2O  (OFF_WFC + DOUT * WFC_STRIDE)
#define OFF_BFC   (OFF_BH2O + DMID)
#define OFF_BSUM  (OFF_BFC + DOUT)
#define SMEM_FLOATS (OFF_BSUM + DH)
#define SMEM_BYTES  (SMEM_FLOATS * 4)

// Device scratch (padded +4 rows for harmless OOB prefetch)
__device__ float g_Wcomb[(KTOT + 4) * DH];
__device__ float g_Wh2oT[(DH + 4) * DMID];
__device__ float g_bsum[DH];

// ---- packed f32x2 helpers (sm_103a FFMA2) ----
__device__ __forceinline__ unsigned long long packf2(float f) {
    unsigned long long d;
    asm("mov.b64 %0, {%1, %1};" : "=l"(d) : "f"(f));
    return d;
}
__device__ __forceinline__ void ffma2(unsigned long long& c,
                                      unsigned long long a,
                                      unsigned long long b) {
    asm("fma.rn.f32x2 %0, %1, %2, %0;" : "+l"(c) : "l"(a), "l"(b));
}
__device__ __forceinline__ float2 unpackf2(unsigned long long p) {
    float2 r;
    asm("mov.b64 {%0, %1}, %2;" : "=f"(r.x), "=f"(r.y) : "l"(p));
    return r;
}

__global__ void prep_kernel(const float* __restrict__ Wi2h,
                            const float* __restrict__ bi2h,
                            const float* __restrict__ Wh2h,
                            const float* __restrict__ bh2h,
                            const float* __restrict__ Wh2o) {
    const int stride = gridDim.x * blockDim.x;
    const int tid = blockIdx.x * blockDim.x + threadIdx.x;
    for (int i = tid; i < DH * DIN; i += stride) {        // Wi2h [256][64]
        int c = i / DIN, k = i % DIN;
        g_Wcomb[k * DH + c] = Wi2h[i];
    }
    for (int i = tid; i < DH * DH; i += stride) {         // Wh2h [256][256]
        int c = i / DH, k = i % DH;
        g_Wcomb[(DIN + k) * DH + c] = Wh2h[i];
    }
    for (int i = tid; i < DMID * DH; i += stride) {       // Wh2o [64][256]
        int c = i / DH, k = i % DH;
        g_Wh2oT[k * DMID + c] = Wh2o[i];
    }
    for (int i = tid; i < DH; i += stride)
        g_bsum[i] = bi2h[i] + bh2h[i];
}

// A-tile load: 8 rows at column k -> 4 packed row-pairs
#define LDA1(dst, k) do {                                                          \
    ulonglong2 q0 = *reinterpret_cast<const ulonglong2*>(Ap + (k) * AT_STRIDE);    \
    ulonglong2 q1 = *reinterpret_cast<const ulonglong2*>(Ap + (k) * AT_STRIDE + 4);\
    dst[0] = q0.x; dst[1] = q0.y; dst[2] = q1.x; dst[3] = q1.y; } while (0)

#define LDW1(w0, w1, k) do {                                                       \
    w0 = __ldg(reinterpret_cast<const float4*>(Wp + (size_t)(k) * DH));            \
    w1 = __ldg(reinterpret_cast<const float4*>(Wp + (size_t)(k) * DH + 4)); } while (0)

#define COMP1(ap, w0, w1) do {                                                     \
    unsigned long long wq[8];                                                      \
    wq[0] = packf2(w0.x); wq[1] = packf2(w0.y);                                    \
    wq[2] = packf2(w0.z); wq[3] = packf2(w0.w);                                    \
    wq[4] = packf2(w1.x); wq[5] = packf2(w1.y);                                    \
    wq[6] = packf2(w1.z); wq[7] = packf2(w1.w);                                    \
    _Pragma("unroll")                                                              \
    for (int ip_ = 0; ip_ < 4; ++ip_)                                              \
        _Pragma("unroll")                                                          \
        for (int j_ = 0; j_ < 8; ++j_)                                             \
            ffma2(acc[ip_][j_], ap[ip_], wq[j_]); } while (0)

#define LDA2(dst, k) do {                                                          \
    ulonglong2 q0 = *reinterpret_cast<const ulonglong2*>(Ap2 + (k) * AT_STRIDE);   \
    ulonglong2 q1 = *reinterpret_cast<const ulonglong2*>(Ap2 + (k) * AT_STRIDE + 4);\
    dst[0] = q0.x; dst[1] = q0.y; dst[2] = q1.x; dst[3] = q1.y; } while (0)

#define COMP2(ap, w) do {                                                          \
    unsigned long long wq0 = packf2(w.x), wq1 = packf2(w.y);                       \
    _Pragma("unroll")                                                              \
    for (int ip_ = 0; ip_ < 4; ++ip_) {                                            \
        ffma2(acc2[ip_][0], ap[ip_], wq0);                                         \
        ffma2(acc2[ip_][1], ap[ip_], wq1); } } while (0)

__global__ void __launch_bounds__(NTHREADS, 2)
rnn_kernel(const float* __restrict__ x,
           const float* __restrict__ hc1,
           const float* __restrict__ Wfc,
           const float* __restrict__ bh2o,
           const float* __restrict__ bfc,
           float* __restrict__ out) {
    extern __shared__ float sm[];
    float* shAT  = sm + OFF_AT;
    float* sms   = sm + OFF_M;
    float* swfc  = sm + OFF_WFC;
    float* sbh2o = sm + OFF_BH2O;
    float* sbfc  = sm + OFF_BFC;
    float* sbsum = sm + OFF_BSUM;

    const int tid  = threadIdx.x;
    const int w    = tid >> 5;
    const int lane = tid & 31;
    const int g    = lane >> 2;
    const int aoff = ROFF(g * 8);
    const int cbase = w * 32 + (lane & 3) * 8;
    const int cb2   = w * 8  + (lane & 3) * 2;
    const int gbase = blockIdx.x * ROWS_PER_CTA;

    {
        int c = tid >> 6, k = tid & 63;
        swfc[c * WFC_STRIDE + k] = Wfc[c * DMID + k];
        if (tid < DMID) sbh2o[tid] = bh2o[tid];
        if (tid < DOUT) sbfc[tid]  = bfc[tid];
        sbsum[tid] = g_bsum[tid];
    }

    for (int idx = tid; idx < ROWS_PER_CTA * (DH / 4); idx += NTHREADS) {
        int r = idx & 63, q = idx >> 6;
        float4 v = *reinterpret_cast<const float4*>(hc1 + (size_t)(gbase + r) * DH + q * 4);
        int ro = ROFF(r);
        shAT[(DIN + q * 4 + 0) * AT_STRIDE + ro] = v.x;
        shAT[(DIN + q * 4 + 1) * AT_STRIDE + ro] = v.y;
        shAT[(DIN + q * 4 + 2) * AT_STRIDE + ro] = v.z;
        shAT[(DIN + q * 4 + 3) * AT_STRIDE + ro] = v.w;
    }
    __syncthreads();

    float* outseq = out;
    float* hfin   = out + (size_t)T_STEPS * B_SIZE * DOUT;

    for (int t = 0; t < T_STEPS; ++t) {
        // ---- stage x_t^T ----
        const float* xt = x + ((size_t)t * B_SIZE + gbase) * DIN;
        for (int idx = tid; idx < ROWS_PER_CTA * (DIN / 4); idx += NTHREADS) {
            int r = idx & 63, q = idx >> 6;
            float4 v = *reinterpret_cast<const float4*>(xt + (size_t)r * DIN + q * 4);
            int ro = ROFF(r);
            shAT[(q * 4 + 0) * AT_STRIDE + ro] = v.x;
            shAT[(q * 4 + 1) * AT_STRIDE + ro] = v.y;
            shAT[(q * 4 + 2) * AT_STRIDE + ro] = v.z;
            shAT[(q * 4 + 3) * AT_STRIDE + ro] = v.w;
        }
        __syncthreads();   // [A]

        // ---- GEMM1: packed row-pair accumulators, 4-stage pipelined k loop ----
        unsigned long long acc[4][8];
        #pragma unroll
        for (int j = 0; j < 8; ++j) {
            unsigned long long b = packf2(sbsum[cbase + j]);
            acc[0][j] = b; acc[1][j] = b; acc[2][j] = b; acc[3][j] = b;
        }

        {
            const float* Ap = shAT + aoff;
            const float* Wp = g_Wcomb + cbase;
            unsigned long long A0[4], A1[4];
            float4 wa0, wa1, wb0, wb1, wc0, wc1, wd0, wd1;
            LDA1(A0, 0);
            LDW1(wa0, wa1, 0);
            LDW1(wb0, wb1, 1);
            #pragma unroll 1
            for (int k = 0; k < KTOT; k += 4) {
                LDA1(A1, k + 1);
                LDW1(wc0, wc1, k + 2);
                LDW1(wd0, wd1, k + 3);
                COMP1(A0, wa0, wa1);
                LDA1(A0, k + 2);
                COMP1(A1, wb0, wb1);
                LDA1(A1, k + 3);
                LDW1(wa0, wa1, k + 4);
                LDW1(wb0, wb1, k + 5);
                COMP1(A0, wc0, wc1);
                LDA1(A0, k + 4);
                COMP1(A1, wd0, wd1);
            }
        }

        // unpack + tanh
        float accf[8][8];
        #pragma unroll
        for (int ip = 0; ip < 4; ++ip)
            #pragma unroll
            for (int j = 0; j < 8; ++j) {
                float2 v = unpackf2(acc[ip][j]);
                accf[2 * ip + 0][j] = tanhf(v.x);
                accf[2 * ip + 1][j] = tanhf(v.y);
            }

        __syncthreads();   // [B]

        #pragma unroll
        for (int j = 0; j < 8; ++j) {
            int c = cbase + j;
            float4 lo = make_float4(accf[0][j], accf[1][j], accf[2][j], accf[3][j]);
            float4 hi = make_float4(accf[4][j], accf[5][j], accf[6][j], accf[7][j]);
            *reinterpret_cast<float4*>(&shAT[(DIN + c) * AT_STRIDE + aoff])     = lo;
            *reinterpret_cast<float4*>(&shAT[(DIN + c) * AT_STRIDE + aoff + 4]) = hi;
        }
        __syncthreads();   // [C]

        // ---- GEMM2: [64x256]x[256x64], packed pairs, pipelined ----
        unsigned long long acc2[4][2];
        {
            unsigned long long b0 = packf2(sbh2o[cb2]);
            unsigned long long b1 = packf2(sbh2o[cb2 + 1]);
            #pragma unroll
            for (int ip = 0; ip < 4; ++ip) { acc2[ip][0] = b0; acc2[ip][1] = b1; }
        }
        {
            const float* Ap2 = shAT + (size_t)DIN * AT_STRIDE + aoff;
            const float* Wp2 = g_Wh2oT + cb2;
            unsigned long long A0[4], A1[4];
            float2 wa, wb, wc, wd;
            LDA2(A0, 0);
            wa = __ldg(reinterpret_cast<const float2*>(Wp2));
            wb = __ldg(reinterpret_cast<const float2*>(Wp2 + DMID));
            #pragma unroll 1
            for (int k = 0; k < DH; k += 4) {
                LDA2(A1, k + 1);
                wc = __ldg(reinterpret_cast<const float2*>(Wp2 + (size_t)(k + 2) * DMID));
                wd = __ldg(reinterpret_cast<const float2*>(Wp2 + (size_t)(k + 3) * DMID));
                COMP2(A0, wa);
                LDA2(A0, k + 2);
                COMP2(A1, wb);
                LDA2(A1, k + 3);
                wa = __ldg(reinterpret_cast<const float2*>(Wp2 + (size_t)(k + 4) * DMID));
                wb = __ldg(reinterpret_cast<const float2*>(Wp2 + (size_t)(k + 5) * DMID));
                COMP2(A0, wc);
                LDA2(A0, k + 4);
                COMP2(A1, wd);
            }
        }
        {
            int rg = g * 8;
            #pragma unroll
            for (int ip = 0; ip < 4; ++ip) {
                float2 v0 = unpackf2(acc2[ip][0]);
                float2 v1 = unpackf2(acc2[ip][1]);
                sms[(rg + 2 * ip + 0) * SM_STRIDE + cb2]     = tanhf(v0.x);
                sms[(rg + 2 * ip + 1) * SM_STRIDE + cb2]     = tanhf(v0.y);
                sms[(rg + 2 * ip + 0) * SM_STRIDE + cb2 + 1] = tanhf(v1.x);
                sms[(rg + 2 * ip + 1) * SM_STRIDE + cb2 + 1] = tanhf(v1.y);
            }
        }
        __syncthreads();   // [D]

        // ---- GEMM3 ----
        {
            const int row = tid >> 2;
            const int col = tid & 3;
            float a3 = sbfc[col];
            const float* mrow = &sms[row * SM_STRIDE];
            const float* wrow = &swfc[col * WFC_STRIDE];
            #pragma unroll 8
            for (int k = 0; k < DMID; ++k)
                a3 = fmaf(mrow[k], wrow[k], a3);
            outseq[((size_t)t * B_SIZE + gbase + row) * DOUT + col] = a3;
        }
    }

    __syncthreads();
    for (int idx = tid; idx < ROWS_PER_CTA * (DH / 4); idx += NTHREADS) {
        int r = idx & 63, q = idx >> 6;
        int ro = ROFF(r);
        float4 v;
        v.x = shAT[(DIN + q * 4 + 0) * AT_STRIDE + ro];
        v.y = shAT[(DIN + q * 4 + 1) * AT_STRIDE + ro];
        v.z = shAT[(DIN + q * 4 + 2) * AT_STRIDE + ro];
        v.w = shAT[(DIN + q * 4 + 3) * AT_STRIDE + ro];
        *reinterpret_cast<float4*>(hfin + (size_t)(gbase + r) * DH + q * 4) = v;
    }
}

extern "C" void kernel_launch(void* const* d_in, const int* in_sizes, int n_in,
                              void* d_out, int out_size) {
    const float* x    = (const float*)d_in[0];
    const float* hc1  = (const float*)d_in[1];
    const float* Wi2h = (const float*)d_in[2];
    const float* bi2h = (const float*)d_in[3];
    const float* Wh2h = (const float*)d_in[4];
    const float* bh2h = (const float*)d_in[5];
    const float* Wh2o = (const float*)d_in[6];
    const float* bh2o = (const float*)d_in[7];
    const float* Wfc  = (const float*)d_in[8];
    const float* bfc  = (const float*)d_in[9];
    float* out = (float*)d_out;

    cudaFuncSetAttribute(rnn_kernel, cudaFuncAttributeMaxDynamicSharedMemorySize, SMEM_BYTES);

    prep_kernel<<<64, 256>>>(Wi2h, bi2h, Wh2h, bh2h, Wh2o);
    rnn_kernel<<<NBLOCKS, NTHREADS, SMEM_BYTES>>>(x, hc1, Wfc, bh2o, bfc, out);
}

// round 5
// speedup vs baseline: 5.5647x; 2.2895x over previous
#include <cuda_runtime.h>
#include <cuda_bf16.h>
#include <cstdint>
#include <cstddef>

#define T_STEPS 16
#define B_SIZE  16384
#define DIN     64
#define DH      256
#define DMID    64
#define DOUT    4
#define M_CTA   64
#define NCTAS   (B_SIZE / M_CTA)   // 256
#define NTH     256

#define HKP 128   // h k-pairs per row
#define XKP 32    // x k-pairs per row

// SMEM word offsets
#define H1_OFF   0
#define H2_OFF   (H1_OFF + 64 * HKP)
#define X1_OFF   (H2_OFF + 64 * HKP)
#define X2_OFF   (X1_OFF + 64 * XKP)
#define SMS_OFF  (X2_OFF + 64 * XKP)      // mid f32 [64][68]
#define WFC_OFF  (SMS_OFF + 64 * 68)
#define BH2O_OFF (WFC_OFF + 4 * 65)
#define BFC_OFF  (BH2O_OFF + 64)
#define BSUM_OFF (BFC_OFF + 4)
#define SMEM_WORDS (BSUM_OFF + 256)
#define SMEM_BYTES (SMEM_WORDS * 4)

// Pre-packed weight fragments (u32 = 2 bf16), +1 kk pad for prefetch clamp safety
__device__ uint32_t g_W1[21 * 8 * 2 * 32 * 4];   // GEMM1 hi split [kk][w][p][lane][4]
__device__ uint32_t g_W2[21 * 8 * 2 * 32 * 4];   // GEMM1 lo split
__device__ uint32_t g_Wo1[17 * 4 * 32 * 4];      // GEMM2 hi split [kk][wn][lane][4]
__device__ uint32_t g_Wo2[17 * 4 * 32 * 4];
__device__ float g_bsum[DH];

__device__ __forceinline__ uint32_t pk(__nv_bfloat16 lo, __nv_bfloat16 hi) {
    return (uint32_t)__bfloat16_as_ushort(lo) | ((uint32_t)__bfloat16_as_ushort(hi) << 16);
}
__device__ __forceinline__ int hidx(int row, int kp) { return row * HKP + (kp ^ ((row & 7) << 2)); }
__device__ __forceinline__ int xidx(int row, int kp) { return row * XKP + (kp ^ ((row & 7) << 2)); }

#define MMA(d, A0, A1_, A2_, A3_, b0, b1)                                         \
    asm volatile("mma.sync.aligned.m16n8k16.row.col.f32.bf16.bf16.f32 "           \
                 "{%0,%1,%2,%3},{%4,%5,%6,%7},{%8,%9},{%0,%1,%2,%3};"             \
                 : "+f"(d[0]), "+f"(d[1]), "+f"(d[2]), "+f"(d[3])                 \
                 : "r"(A0), "r"(A1_), "r"(A2_), "r"(A3_), "r"(b0), "r"(b1))

// Load A fragment (4 words) for m-tile mt at kpair base kp0 from word array arr
#define LDA_H(arr, kp0, mt, A0, A1_, A2_, A3_) do {                               \
    int r0_ = (mt) * 16 + g, r1_ = r0_ + 8;                                       \
    A0 = arr[hidx(r0_, (kp0) + t)];  A1_ = arr[hidx(r1_, (kp0) + t)];             \
    A2_ = arr[hidx(r0_, (kp0) + t + 4)]; A3_ = arr[hidx(r1_, (kp0) + t + 4)]; } while (0)
#define LDA_X(arr, kp0, mt, A0, A1_, A2_, A3_) do {                               \
    int r0_ = (mt) * 16 + g, r1_ = r0_ + 8;                                       \
    A0 = arr[xidx(r0_, (kp0) + t)];  A1_ = arr[xidx(r1_, (kp0) + t)];             \
    A2_ = arr[xidx(r0_, (kp0) + t + 4)]; A3_ = arr[xidx(r1_, (kp0) + t + 4)]; } while (0)

__global__ void prep_kernel(const float* __restrict__ Wi2h,
                            const float* __restrict__ bi2h,
                            const float* __restrict__ Wh2h,
                            const float* __restrict__ bh2h,
                            const float* __restrict__ Wh2o) {
    const int stride = gridDim.x * blockDim.x;
    const int tid = blockIdx.x * blockDim.x + threadIdx.x;
    // GEMM1 combined W [n<256][k<320]: k<64 -> Wi2h, else Wh2h
    for (int i = tid; i < 20 * 8 * 2 * 32 * 4; i += stride) {
        int word = i & 3, lane = (i >> 2) & 31, p = (i >> 7) & 1, w = (i >> 8) & 7, kk = i >> 11;
        int gg = lane >> 2, tt = lane & 3;
        int n = w * 32 + p * 16 + ((word >> 1) ? 8 : 0) + gg;
        int k = kk * 16 + tt * 2 + ((word & 1) ? 8 : 0);
        float v0, v1;
        if (k < DIN) { v0 = Wi2h[n * DIN + k]; v1 = Wi2h[n * DIN + k + 1]; }
        else         { v0 = Wh2h[n * DH + k - DIN]; v1 = Wh2h[n * DH + k - DIN + 1]; }
        __nv_bfloat16 h0 = __float2bfloat16_rn(v0), h1 = __float2bfloat16_rn(v1);
        g_W1[i] = pk(h0, h1);
        g_W2[i] = pk(__float2bfloat16_rn(v0 - __bfloat162float(h0)),
                     __float2bfloat16_rn(v1 - __bfloat162float(h1)));
    }
    // GEMM2 W_h2o [n<64][k<256]
    for (int i = tid; i < 16 * 4 * 32 * 4; i += stride) {
        int word = i & 3, lane = (i >> 2) & 31, wn = (i >> 7) & 3, kk = i >> 9;
        int gg = lane >> 2, tt = lane & 3;
        int n = wn * 16 + ((word >> 1) ? 8 : 0) + gg;
        int k = kk * 16 + tt * 2 + ((word & 1) ? 8 : 0);
        float v0 = Wh2o[n * DH + k], v1 = Wh2o[n * DH + k + 1];
        __nv_bfloat16 h0 = __float2bfloat16_rn(v0), h1 = __float2bfloat16_rn(v1);
        g_Wo1[i] = pk(h0, h1);
        g_Wo2[i] = pk(__float2bfloat16_rn(v0 - __bfloat162float(h0)),
                      __float2bfloat16_rn(v1 - __bfloat162float(h1)));
    }
    for (int i = tid; i < DH; i += stride) g_bsum[i] = bi2h[i] + bh2h[i];
}

__global__ void __launch_bounds__(NTH, 2)
rnn_kernel(const float* __restrict__ x,
           const float* __restrict__ hc1,
           const float* __restrict__ Wfc,
           const float* __restrict__ bh2o,
           const float* __restrict__ bfc,
           float* __restrict__ out) {
    extern __shared__ uint32_t sm[];
    float* smf = (float*)sm;
    uint32_t* H1 = sm + H1_OFF;
    uint32_t* H2 = sm + H2_OFF;
    uint32_t* X1 = sm + X1_OFF;
    uint32_t* X2 = sm + X2_OFF;

    const int tid = threadIdx.x, w = tid >> 5, lane = tid & 31;
    const int g = lane >> 2, t = lane & 3;
    const int wn = w & 3, mh = w >> 2;
    const int gbase = blockIdx.x * M_CTA;

    { // constants
        int c = tid >> 6, k = tid & 63;
        smf[WFC_OFF + c * 65 + k] = Wfc[c * DMID + k];
        if (tid < DMID) smf[BH2O_OFF + tid] = bh2o[tid];
        if (tid < DOUT) smf[BFC_OFF + tid] = bfc[tid];
        smf[BSUM_OFF + tid] = g_bsum[tid];
    }
    // stage hc1 split into H1/H2
    for (int i = tid; i < 64 * HKP; i += NTH) {
        int row = i >> 7, kp = i & 127;
        float2 v = *(const float2*)(hc1 + (size_t)(gbase + row) * DH + kp * 2);
        __nv_bfloat16 b0 = __float2bfloat16_rn(v.x), b1 = __float2bfloat16_rn(v.y);
        H1[hidx(row, kp)] = pk(b0, b1);
        H2[hidx(row, kp)] = pk(__float2bfloat16_rn(v.x - __bfloat162float(b0)),
                               __float2bfloat16_rn(v.y - __bfloat162float(b1)));
    }
    __syncthreads();

    // per-thread bias registers
    float bias1[4][2], bias2[2][2];
    #pragma unroll
    for (int nt = 0; nt < 4; ++nt) {
        int n0 = w * 32 + nt * 8 + 2 * t;
        bias1[nt][0] = smf[BSUM_OFF + n0]; bias1[nt][1] = smf[BSUM_OFF + n0 + 1];
    }
    #pragma unroll
    for (int nt = 0; nt < 2; ++nt) {
        int n0 = wn * 16 + nt * 8 + 2 * t;
        bias2[nt][0] = smf[BH2O_OFF + n0]; bias2[nt][1] = smf[BH2O_OFF + n0 + 1];
    }

    float* outseq = out;
    float* hfin = out + (size_t)T_STEPS * B_SIZE * DOUT;

    for (int ts = 0; ts < T_STEPS; ++ts) {
        // ---- stage x split ----
        const float* xt = x + ((size_t)ts * B_SIZE + gbase) * DIN;
        for (int i = tid; i < 64 * XKP; i += NTH) {
            int row = i >> 5, kp = i & 31;
            float2 v = *(const float2*)(xt + (size_t)row * DIN + kp * 2);
            __nv_bfloat16 b0 = __float2bfloat16_rn(v.x), b1 = __float2bfloat16_rn(v.y);
            X1[xidx(row, kp)] = pk(b0, b1);
            X2[xidx(row, kp)] = pk(__float2bfloat16_rn(v.x - __bfloat162float(b0)),
                                   __float2bfloat16_rn(v.y - __bfloat162float(b1)));
        }
        __syncthreads();   // [A]

        // ---- GEMM1: warp = n-slice of 32 (4 n-tiles), all 4 m-tiles ----
        float acc[4][4][4];
        #pragma unroll
        for (int mt = 0; mt < 4; ++mt)
            #pragma unroll
            for (int nt = 0; nt < 4; ++nt) {
                acc[mt][nt][0] = bias1[nt][0]; acc[mt][nt][1] = bias1[nt][1];
                acc[mt][nt][2] = bias1[nt][0]; acc[mt][nt][3] = bias1[nt][1];
            }

        // pass 1: W1 with A1 and A2
        {
            uint4 B0 = *(const uint4*)(g_W1 + ((0 * 8 + w) * 2 + 0) * 128 + lane * 4);
            uint4 B1 = *(const uint4*)(g_W1 + ((0 * 8 + w) * 2 + 1) * 128 + lane * 4);
            #pragma unroll 2
            for (int kk = 0; kk < 20; ++kk) {
                uint4 nB0 = *(const uint4*)(g_W1 + (((kk + 1) * 8 + w) * 2 + 0) * 128 + lane * 4);
                uint4 nB1 = *(const uint4*)(g_W1 + (((kk + 1) * 8 + w) * 2 + 1) * 128 + lane * 4);
                uint32_t a0, a1, a2, a3;
                if (kk < 4) {
                    int kp0 = kk * 8;
                    #pragma unroll
                    for (int mt = 0; mt < 4; ++mt) {
                        LDA_X(X1, kp0, mt, a0, a1, a2, a3);
                        MMA(acc[mt][0], a0, a1, a2, a3, B0.x, B0.y);
                        MMA(acc[mt][1], a0, a1, a2, a3, B0.z, B0.w);
                        MMA(acc[mt][2], a0, a1, a2, a3, B1.x, B1.y);
                        MMA(acc[mt][3], a0, a1, a2, a3, B1.z, B1.w);
                        LDA_X(X2, kp0, mt, a0, a1, a2, a3);
                        MMA(acc[mt][0], a0, a1, a2, a3, B0.x, B0.y);
                        MMA(acc[mt][1], a0, a1, a2, a3, B0.z, B0.w);
                        MMA(acc[mt][2], a0, a1, a2, a3, B1.x, B1.y);
                        MMA(acc[mt][3], a0, a1, a2, a3, B1.z, B1.w);
                    }
                } else {
                    int kp0 = (kk - 4) * 8;
                    #pragma unroll
                    for (int mt = 0; mt < 4; ++mt) {
                        LDA_H(H1, kp0, mt, a0, a1, a2, a3);
                        MMA(acc[mt][0], a0, a1, a2, a3, B0.x, B0.y);
                        MMA(acc[mt][1], a0, a1, a2, a3, B0.z, B0.w);
                        MMA(acc[mt][2], a0, a1, a2, a3, B1.x, B1.y);
                        MMA(acc[mt][3], a0, a1, a2, a3, B1.z, B1.w);
                        LDA_H(H2, kp0, mt, a0, a1, a2, a3);
                        MMA(acc[mt][0], a0, a1, a2, a3, B0.x, B0.y);
                        MMA(acc[mt][1], a0, a1, a2, a3, B0.z, B0.w);
                        MMA(acc[mt][2], a0, a1, a2, a3, B1.x, B1.y);
                        MMA(acc[mt][3], a0, a1, a2, a3, B1.z, B1.w);
                    }
                }
                B0 = nB0; B1 = nB1;
            }
        }
        // pass 2: W2 with A1
        {
            uint4 B0 = *(const uint4*)(g_W2 + ((0 * 8 + w) * 2 + 0) * 128 + lane * 4);
            uint4 B1 = *(const uint4*)(g_W2 + ((0 * 8 + w) * 2 + 1) * 128 + lane * 4);
            #pragma unroll 2
            for (int kk = 0; kk < 20; ++kk) {
                uint4 nB0 = *(const uint4*)(g_W2 + (((kk + 1) * 8 + w) * 2 + 0) * 128 + lane * 4);
                uint4 nB1 = *(const uint4*)(g_W2 + (((kk + 1) * 8 + w) * 2 + 1) * 128 + lane * 4);
                uint32_t a0, a1, a2, a3;
                #pragma unroll
                for (int mt = 0; mt < 4; ++mt) {
                    if (kk < 4) { LDA_X(X1, kk * 8, mt, a0, a1, a2, a3); }
                    else        { LDA_H(H1, (kk - 4) * 8, mt, a0, a1, a2, a3); }
                    MMA(acc[mt][0], a0, a1, a2, a3, B0.x, B0.y);
                    MMA(acc[mt][1], a0, a1, a2, a3, B0.z, B0.w);
                    MMA(acc[mt][2], a0, a1, a2, a3, B1.x, B1.y);
                    MMA(acc[mt][3], a0, a1, a2, a3, B1.z, B1.w);
                }
                B0 = nB0; B1 = nB1;
            }
        }

        __syncthreads();   // [B] all H/X reads done

        // ---- GEMM1 epilogue: tanh, split, write back to H1/H2 ----
        #pragma unroll
        for (int mt = 0; mt < 4; ++mt)
            #pragma unroll
            for (int nt = 0; nt < 4; ++nt) {
                float v0 = tanhf(acc[mt][nt][0]), v1 = tanhf(acc[mt][nt][1]);
                float v2 = tanhf(acc[mt][nt][2]), v3 = tanhf(acc[mt][nt][3]);
                int kp = w * 16 + nt * 4 + t;
                int r0 = mt * 16 + g, r1 = r0 + 8;
                __nv_bfloat16 c0 = __float2bfloat16_rn(v0), c1 = __float2bfloat16_rn(v1);
                __nv_bfloat16 c2 = __float2bfloat16_rn(v2), c3 = __float2bfloat16_rn(v3);
                H1[hidx(r0, kp)] = pk(c0, c1);
                H1[hidx(r1, kp)] = pk(c2, c3);
                H2[hidx(r0, kp)] = pk(__float2bfloat16_rn(v0 - __bfloat162float(c0)),
                                      __float2bfloat16_rn(v1 - __bfloat162float(c1)));
                H2[hidx(r1, kp)] = pk(__float2bfloat16_rn(v2 - __bfloat162float(c2)),
                                      __float2bfloat16_rn(v3 - __bfloat162float(c3)));
            }
        __syncthreads();   // [C] h_new visible

        // ---- GEMM2: warp = (mh half of M, wn n-slice of 16) ----
        float acc2[2][2][4];
        #pragma unroll
        for (int mt = 0; mt < 2; ++mt)
            #pragma unroll
            for (int nt = 0; nt < 2; ++nt) {
                acc2[mt][nt][0] = bias2[nt][0]; acc2[mt][nt][1] = bias2[nt][1];
                acc2[mt][nt][2] = bias2[nt][0]; acc2[mt][nt][3] = bias2[nt][1];
            }
        {
            uint4 B0 = *(const uint4*)(g_Wo1 + (0 * 4 + wn) * 128 + lane * 4);
            #pragma unroll 2
            for (int kk = 0; kk < 16; ++kk) {
                uint4 nB0 = *(const uint4*)(g_Wo1 + ((kk + 1) * 4 + wn) * 128 + lane * 4);
                uint32_t a0, a1, a2, a3;
                #pragma unroll
                for (int mt = 0; mt < 2; ++mt) {
                    LDA_H(H1, kk * 8, (2 * mh + mt), a0, a1, a2, a3);
                    MMA(acc2[mt][0], a0, a1, a2, a3, B0.x, B0.y);
                    MMA(acc2[mt][1], a0, a1, a2, a3, B0.z, B0.w);
                    LDA_H(H2, kk * 8, (2 * mh + mt), a0, a1, a2, a3);
                    MMA(acc2[mt][0], a0, a1, a2, a3, B0.x, B0.y);
                    MMA(acc2[mt][1], a0, a1, a2, a3, B0.z, B0.w);
                }
                B0 = nB0;
            }
            B0 = *(const uint4*)(g_Wo2 + (0 * 4 + wn) * 128 + lane * 4);
            #pragma unroll 2
            for (int kk = 0; kk < 16; ++kk) {
                uint4 nB0 = *(const uint4*)(g_Wo2 + ((kk + 1) * 4 + wn) * 128 + lane * 4);
                uint32_t a0, a1, a2, a3;
                #pragma unroll
                for (int mt = 0; mt < 2; ++mt) {
                    LDA_H(H1, kk * 8, (2 * mh + mt), a0, a1, a2, a3);
                    MMA(acc2[mt][0], a0, a1, a2, a3, B0.x, B0.y);
                    MMA(acc2[mt][1], a0, a1, a2, a3, B0.z, B0.w);
                }
                B0 = nB0;
            }
        }
        // epilogue: tanh -> mid f32 in sms
        #pragma unroll
        for (int mt = 0; mt < 2; ++mt)
            #pragma unroll
            for (int nt = 0; nt < 2; ++nt) {
                int n0 = wn * 16 + nt * 8 + 2 * t;
                int r0 = 32 * mh + 16 * mt + g, r1 = r0 + 8;
                smf[SMS_OFF + r0 * 68 + n0]     = tanhf(acc2[mt][nt][0]);
                smf[SMS_OFF + r0 * 68 + n0 + 1] = tanhf(acc2[mt][nt][1]);
                smf[SMS_OFF + r1 * 68 + n0]     = tanhf(acc2[mt][nt][2]);
                smf[SMS_OFF + r1 * 68 + n0 + 1] = tanhf(acc2[mt][nt][3]);
            }
        __syncthreads();   // [D] mid ready

        // ---- GEMM3: one output per thread ----
        {
            const int row = tid >> 2, col = tid & 3;
            float a3 = smf[BFC_OFF + col];
            const float* mrow = &smf[SMS_OFF + row * 68];
            const float* wrow = &smf[WFC_OFF + col * 65];
            #pragma unroll 8
            for (int k = 0; k < DMID; ++k)
                a3 = fmaf(mrow[k], wrow[k], a3);
            outseq[((size_t)ts * B_SIZE + gbase + row) * DOUT + col] = a3;
        }
    }

    __syncthreads();
    // ---- h_final = H1 + H2 ----
    for (int i = tid; i < 64 * HKP; i += NTH) {
        int row = i >> 7, kp = i & 127;
        uint32_t w1 = H1[hidx(row, kp)], w2 = H2[hidx(row, kp)];
        float2 v;
        v.x = __bfloat162float(__ushort_as_bfloat16((unsigned short)(w1 & 0xFFFF))) +
              __bfloat162float(__ushort_as_bfloat16((unsigned short)(w2 & 0xFFFF)));
        v.y = __bfloat162float(__ushort_as_bfloat16((unsigned short)(w1 >> 16))) +
              __bfloat162float(__ushort_as_bfloat16((unsigned short)(w2 >> 16)));
        *(float2*)(hfin + (size_t)(gbase + row) * DH + kp * 2) = v;
    }
}

extern "C" void kernel_launch(void* const* d_in, const int* in_sizes, int n_in,
                              void* d_out, int out_size) {
    const float* x    = (const float*)d_in[0];
    const float* hc1  = (const float*)d_in[1];
    const float* Wi2h = (const float*)d_in[2];
    const float* bi2h = (const float*)d_in[3];
    const float* Wh2h = (const float*)d_in[4];
    const float* bh2h = (const float*)d_in[5];
    const float* Wh2o = (const float*)d_in[6];
    const float* bh2o = (const float*)d_in[7];
    const float* Wfc  = (const float*)d_in[8];
    const float* bfc  = (const float*)d_in[9];
    float* out = (float*)d_out;

    cudaFuncSetAttribute(rnn_kernel, cudaFuncAttributeMaxDynamicSharedMemorySize, SMEM_BYTES);

    prep_kernel<<<64, 256>>>(Wi2h, bi2h, Wh2h, bh2h, Wh2o);
    rnn_kernel<<<NCTAS, NTH, SMEM_BYTES>>>(x, hc1, Wfc, bh2o, bfc, out);
}

// round 6
// speedup vs baseline: 6.2719x; 1.1271x over previous
#include <cuda_runtime.h>
#include <cuda_bf16.h>
#include <cstdint>
#include <cstddef>

#define T_STEPS 16
#define B_SIZE  16384
#define DIN     64
#define DH      256
#define DMID    64
#define DOUT    4
#define M_CTA   64
#define NCTAS   (B_SIZE / M_CTA)   // 256
#define NTH     256

#define HKP 128   // h k-pairs per row
#define XKP 32    // x k-pairs per row

// SMEM word offsets
#define H1_OFF   0
#define H2_OFF   (H1_OFF + 64 * HKP)
#define X1_OFF   (H2_OFF + 64 * HKP)
#define X2_OFF   (X1_OFF + 64 * XKP)
#define SMS_OFF  (X2_OFF + 64 * XKP)      // mid f32 [64][68]
#define WFC_OFF  (SMS_OFF + 64 * 68)
#define BH2O_OFF (WFC_OFF + 4 * 65)
#define BFC_OFF  (BH2O_OFF + 64)
#define BSUM_OFF (BFC_OFF + 4)
#define SMEM_WORDS (BSUM_OFF + 256)
#define SMEM_BYTES (SMEM_WORDS * 4)

// Pre-packed weight fragments (u32 = 2 bf16), +1 kk pad for prefetch clamp safety
__device__ uint32_t g_W1[21 * 8 * 2 * 32 * 4];   // GEMM1 hi split [kk][w][p][lane][4]
__device__ uint32_t g_W2[21 * 8 * 2 * 32 * 4];   // GEMM1 lo split
__device__ uint32_t g_Wo1[17 * 4 * 32 * 4];      // GEMM2 hi split [kk][wn][lane][4]
__device__ uint32_t g_Wo2[17 * 4 * 32 * 4];
__device__ float g_bsum[DH];

__device__ __forceinline__ uint32_t pk(__nv_bfloat16 lo, __nv_bfloat16 hi) {
    return (uint32_t)__bfloat16_as_ushort(lo) | ((uint32_t)__bfloat16_as_ushort(hi) << 16);
}
__device__ __forceinline__ int hidx(int row, int kp) { return row * HKP + (kp ^ ((row & 7) << 2)); }
__device__ __forceinline__ int xidx(int row, int kp) { return row * XKP + (kp ^ ((row & 7) << 2)); }

#define MMA(d, A0, A1_, A2_, A3_, b0, b1)                                         \
    asm volatile("mma.sync.aligned.m16n8k16.row.col.f32.bf16.bf16.f32 "           \
                 "{%0,%1,%2,%3},{%4,%5,%6,%7},{%8,%9},{%0,%1,%2,%3};"             \
                 : "+f"(d[0]), "+f"(d[1]), "+f"(d[2]), "+f"(d[3])                 \
                 : "r"(A0), "r"(A1_), "r"(A2_), "r"(A3_), "r"(b0), "r"(b1))

#define LDSM4(a0, a1, a2, a3, addr)                                               \
    asm volatile("ldmatrix.sync.aligned.m8n8.x4.shared.b16 {%0,%1,%2,%3}, [%4];"  \
                 : "=r"(a0), "=r"(a1), "=r"(a2), "=r"(a3) : "r"(addr))

// byte addr of A fragment: base(hi/lo array) + mt row-block + swizzled k-chunk
#define AH(base, mt, kp0) ((base) + (mt) * (16 * HKP * 4) + (((((kp0) + kadd)) ^ sxor) << 2))
#define AX(base, mt, kp0) ((base) + (mt) * (16 * XKP * 4) + (((((kp0) + kadd)) ^ sxor) << 2))

__global__ void prep_kernel(const float* __restrict__ Wi2h,
                            const float* __restrict__ bi2h,
                            const float* __restrict__ Wh2h,
                            const float* __restrict__ bh2h,
                            const float* __restrict__ Wh2o) {
    const int stride = gridDim.x * blockDim.x;
    const int tid = blockIdx.x * blockDim.x + threadIdx.x;
    for (int i = tid; i < 20 * 8 * 2 * 32 * 4; i += stride) {
        int word = i & 3, lane = (i >> 2) & 31, p = (i >> 7) & 1, w = (i >> 8) & 7, kk = i >> 11;
        int gg = lane >> 2, tt = lane & 3;
        int n = w * 32 + p * 16 + ((word >> 1) ? 8 : 0) + gg;
        int k = kk * 16 + tt * 2 + ((word & 1) ? 8 : 0);
        float v0, v1;
        if (k < DIN) { v0 = Wi2h[n * DIN + k]; v1 = Wi2h[n * DIN + k + 1]; }
        else         { v0 = Wh2h[n * DH + k - DIN]; v1 = Wh2h[n * DH + k - DIN + 1]; }
        __nv_bfloat16 h0 = __float2bfloat16_rn(v0), h1 = __float2bfloat16_rn(v1);
        g_W1[i] = pk(h0, h1);
        g_W2[i] = pk(__float2bfloat16_rn(v0 - __bfloat162float(h0)),
                     __float2bfloat16_rn(v1 - __bfloat162float(h1)));
    }
    for (int i = tid; i < 16 * 4 * 32 * 4; i += stride) {
        int word = i & 3, lane = (i >> 2) & 31, wn = (i >> 7) & 3, kk = i >> 9;
        int gg = lane >> 2, tt = lane & 3;
        int n = wn * 16 + ((word >> 1) ? 8 : 0) + gg;
        int k = kk * 16 + tt * 2 + ((word & 1) ? 8 : 0);
        float v0 = Wh2o[n * DH + k], v1 = Wh2o[n * DH + k + 1];
        __nv_bfloat16 h0 = __float2bfloat16_rn(v0), h1 = __float2bfloat16_rn(v1);
        g_Wo1[i] = pk(h0, h1);
        g_Wo2[i] = pk(__float2bfloat16_rn(v0 - __bfloat162float(h0)),
                      __float2bfloat16_rn(v1 - __bfloat162float(h1)));
    }
    for (int i = tid; i < DH; i += stride) g_bsum[i] = bi2h[i] + bh2h[i];
}

__global__ void __launch_bounds__(NTH, 2)
rnn_kernel(const float* __restrict__ x,
           const float* __restrict__ hc1,
           const float* __restrict__ Wfc,
           const float* __restrict__ bh2o,
           const float* __restrict__ bfc,
           float* __restrict__ out) {
    extern __shared__ uint32_t sm[];
    float* smf = (float*)sm;
    uint32_t* H1 = sm + H1_OFF;
    uint32_t* H2 = sm + H2_OFF;
    uint32_t* X1 = sm + X1_OFF;
    uint32_t* X2 = sm + X2_OFF;

    const int tid = threadIdx.x, w = tid >> 5, lane = tid & 31;
    const int g = lane >> 2, t = lane & 3;
    const int wn = w & 3, mh = w >> 2;
    const int gbase = blockIdx.x * M_CTA;

    // ldmatrix per-thread geometry
    const int rowA = (lane & 7) + ((lane >> 3) & 1) * 8;   // row within 16-row m-tile
    const uint32_t kadd = (lane >> 4) * 4;                 // k-chunk half select
    const uint32_t sxor = (uint32_t)((lane & 7) << 2);     // swizzle for this row

    const uint32_t h1b = (uint32_t)__cvta_generic_to_shared(H1 + rowA * HKP);
    const uint32_t h2b = (uint32_t)__cvta_generic_to_shared(H2 + rowA * HKP);
    const uint32_t x1b = (uint32_t)__cvta_generic_to_shared(X1 + rowA * XKP);
    const uint32_t x2b = (uint32_t)__cvta_generic_to_shared(X2 + rowA * XKP);

    { // constants
        int c = tid >> 6, k = tid & 63;
        smf[WFC_OFF + c * 65 + k] = Wfc[c * DMID + k];
        if (tid < DMID) smf[BH2O_OFF + tid] = bh2o[tid];
        if (tid < DOUT) smf[BFC_OFF + tid] = bfc[tid];
        smf[BSUM_OFF + tid] = g_bsum[tid];
    }
    // stage hc1 split into H1/H2
    for (int i = tid; i < 64 * HKP; i += NTH) {
        int row = i >> 7, kp = i & 127;
        float2 v = *(const float2*)(hc1 + (size_t)(gbase + row) * DH + kp * 2);
        __nv_bfloat16 b0 = __float2bfloat16_rn(v.x), b1 = __float2bfloat16_rn(v.y);
        H1[hidx(row, kp)] = pk(b0, b1);
        H2[hidx(row, kp)] = pk(__float2bfloat16_rn(v.x - __bfloat162float(b0)),
                               __float2bfloat16_rn(v.y - __bfloat162float(b1)));
    }
    __syncthreads();

    float bias1[4][2], bias2[2][2];
    #pragma unroll
    for (int nt = 0; nt < 4; ++nt) {
        int n0 = w * 32 + nt * 8 + 2 * t;
        bias1[nt][0] = smf[BSUM_OFF + n0]; bias1[nt][1] = smf[BSUM_OFF + n0 + 1];
    }
    #pragma unroll
    for (int nt = 0; nt < 2; ++nt) {
        int n0 = wn * 16 + nt * 8 + 2 * t;
        bias2[nt][0] = smf[BH2O_OFF + n0]; bias2[nt][1] = smf[BH2O_OFF + n0 + 1];
    }

    // W fragment base pointers (per warp+lane)
    const uint32_t* W1p  = g_W1  + (w * 2) * 128 + lane * 4;   // +kk*2048, p-> +128
    const uint32_t* W2p  = g_W2  + (w * 2) * 128 + lane * 4;
    const uint32_t* Wo1p = g_Wo1 + wn * 128 + lane * 4;        // +kk*512
    const uint32_t* Wo2p = g_Wo2 + wn * 128 + lane * 4;

    float* outseq = out;
    float* hfin = out + (size_t)T_STEPS * B_SIZE * DOUT;

    for (int ts = 0; ts < T_STEPS; ++ts) {
        // ---- stage x split ----
        const float* xt = x + ((size_t)ts * B_SIZE + gbase) * DIN;
        for (int i = tid; i < 64 * XKP; i += NTH) {
            int row = i >> 5, kp = i & 31;
            float2 v = *(const float2*)(xt + (size_t)row * DIN + kp * 2);
            __nv_bfloat16 b0 = __float2bfloat16_rn(v.x), b1 = __float2bfloat16_rn(v.y);
            X1[xidx(row, kp)] = pk(b0, b1);
            X2[xidx(row, kp)] = pk(__float2bfloat16_rn(v.x - __bfloat162float(b0)),
                                   __float2bfloat16_rn(v.y - __bfloat162float(b1)));
        }
        __syncthreads();   // [A]

        // ---- GEMM1 ----
        float acc[4][4][4];
        #pragma unroll
        for (int mt = 0; mt < 4; ++mt)
            #pragma unroll
            for (int nt = 0; nt < 4; ++nt) {
                acc[mt][nt][0] = bias1[nt][0]; acc[mt][nt][1] = bias1[nt][1];
                acc[mt][nt][2] = bias1[nt][0]; acc[mt][nt][3] = bias1[nt][1];
            }

        // pass 1: W1 with A1 and A2
        {
            uint4 B0 = *(const uint4*)(W1p);
            uint4 B1 = *(const uint4*)(W1p + 128);
            #pragma unroll 2
            for (int kk = 0; kk < 20; ++kk) {
                uint4 nB0 = *(const uint4*)(W1p + (kk + 1) * 2048);
                uint4 nB1 = *(const uint4*)(W1p + (kk + 1) * 2048 + 128);
                uint32_t a0, a1, a2, a3;
                if (kk < 4) {
                    const uint32_t kp0 = kk * 8;
                    #pragma unroll
                    for (int mt = 0; mt < 4; ++mt) {
                        LDSM4(a0, a1, a2, a3, AX(x1b, mt, kp0));
                        MMA(acc[mt][0], a0, a1, a2, a3, B0.x, B0.y);
                        MMA(acc[mt][1], a0, a1, a2, a3, B0.z, B0.w);
                        MMA(acc[mt][2], a0, a1, a2, a3, B1.x, B1.y);
                        MMA(acc[mt][3], a0, a1, a2, a3, B1.z, B1.w);
                        LDSM4(a0, a1, a2, a3, AX(x2b, mt, kp0));
                        MMA(acc[mt][0], a0, a1, a2, a3, B0.x, B0.y);
                        MMA(acc[mt][1], a0, a1, a2, a3, B0.z, B0.w);
                        MMA(acc[mt][2], a0, a1, a2, a3, B1.x, B1.y);
                        MMA(acc[mt][3], a0, a1, a2, a3, B1.z, B1.w);
                    }
                } else {
                    const uint32_t kp0 = (kk - 4) * 8;
                    #pragma unroll
                    for (int mt = 0; mt < 4; ++mt) {
                        LDSM4(a0, a1, a2, a3, AH(h1b, mt, kp0));
                        MMA(acc[mt][0], a0, a1, a2, a3, B0.x, B0.y);
                        MMA(acc[mt][1], a0, a1, a2, a3, B0.z, B0.w);
                        MMA(acc[mt][2], a0, a1, a2, a3, B1.x, B1.y);
                        MMA(acc[mt][3], a0, a1, a2, a3, B1.z, B1.w);
                        LDSM4(a0, a1, a2, a3, AH(h2b, mt, kp0));
                        MMA(acc[mt][0], a0, a1, a2, a3, B0.x, B0.y);
                        MMA(acc[mt][1], a0, a1, a2, a3, B0.z, B0.w);
                        MMA(acc[mt][2], a0, a1, a2, a3, B1.x, B1.y);
                        MMA(acc[mt][3], a0, a1, a2, a3, B1.z, B1.w);
                    }
                }
                B0 = nB0; B1 = nB1;
            }
        }
        // pass 2: W2 with A1
        {
            uint4 B0 = *(const uint4*)(W2p);
            uint4 B1 = *(const uint4*)(W2p + 128);
            #pragma unroll 2
            for (int kk = 0; kk < 20; ++kk) {
                uint4 nB0 = *(const uint4*)(W2p + (kk + 1) * 2048);
                uint4 nB1 = *(const uint4*)(W2p + (kk + 1) * 2048 + 128);
                uint32_t a0, a1, a2, a3;
                #pragma unroll
                for (int mt = 0; mt < 4; ++mt) {
                    if (kk < 4) { LDSM4(a0, a1, a2, a3, AX(x1b, mt, kk * 8)); }
                    else        { LDSM4(a0, a1, a2, a3, AH(h1b, mt, (kk - 4) * 8)); }
                    MMA(acc[mt][0], a0, a1, a2, a3, B0.x, B0.y);
                    MMA(acc[mt][1], a0, a1, a2, a3, B0.z, B0.w);
                    MMA(acc[mt][2], a0, a1, a2, a3, B1.x, B1.y);
                    MMA(acc[mt][3], a0, a1, a2, a3, B1.z, B1.w);
                }
                B0 = nB0; B1 = nB1;
            }
        }

        __syncthreads();   // [B]

        // ---- GEMM1 epilogue ----
        #pragma unroll
        for (int mt = 0; mt < 4; ++mt)
            #pragma unroll
            for (int nt = 0; nt < 4; ++nt) {
                float v0 = tanhf(acc[mt][nt][0]), v1 = tanhf(acc[mt][nt][1]);
                float v2 = tanhf(acc[mt][nt][2]), v3 = tanhf(acc[mt][nt][3]);
                int kp = w * 16 + nt * 4 + t;
                int r0 = mt * 16 + g, r1 = r0 + 8;
                __nv_bfloat16 c0 = __float2bfloat16_rn(v0), c1 = __float2bfloat16_rn(v1);
                __nv_bfloat16 c2 = __float2bfloat16_rn(v2), c3 = __float2bfloat16_rn(v3);
                H1[hidx(r0, kp)] = pk(c0, c1);
                H1[hidx(r1, kp)] = pk(c2, c3);
                H2[hidx(r0, kp)] = pk(__float2bfloat16_rn(v0 - __bfloat162float(c0)),
                                      __float2bfloat16_rn(v1 - __bfloat162float(c1)));
                H2[hidx(r1, kp)] = pk(__float2bfloat16_rn(v2 - __bfloat162float(c2)),
                                      __float2bfloat16_rn(v3 - __bfloat162float(c3)));
            }
        __syncthreads();   // [C]

        // ---- GEMM2 ----
        float acc2[2][2][4];
        #pragma unroll
        for (int mt = 0; mt < 2; ++mt)
            #pragma unroll
            for (int nt = 0; nt < 2; ++nt) {
                acc2[mt][nt][0] = bias2[nt][0]; acc2[mt][nt][1] = bias2[nt][1];
                acc2[mt][nt][2] = bias2[nt][0]; acc2[mt][nt][3] = bias2[nt][1];
            }
        {
            uint4 B0 = *(const uint4*)(Wo1p);
            #pragma unroll 2
            for (int kk = 0; kk < 16; ++kk) {
                uint4 nB0 = *(const uint4*)(Wo1p + (kk + 1) * 512);
                uint32_t a0, a1, a2, a3;
                #pragma unroll
                for (int mt = 0; mt < 2; ++mt) {
                    LDSM4(a0, a1, a2, a3, AH(h1b, (2 * mh + mt), kk * 8));
                    MMA(acc2[mt][0], a0, a1, a2, a3, B0.x, B0.y);
                    MMA(acc2[mt][1], a0, a1, a2, a3, B0.z, B0.w);
                    LDSM4(a0, a1, a2, a3, AH(h2b, (2 * mh + mt), kk * 8));
                    MMA(acc2[mt][0], a0, a1, a2, a3, B0.x, B0.y);
                    MMA(acc2[mt][1], a0, a1, a2, a3, B0.z, B0.w);
                }
                B0 = nB0;
            }
            B0 = *(const uint4*)(Wo2p);
            #pragma unroll 2
            for (int kk = 0; kk < 16; ++kk) {
                uint4 nB0 = *(const uint4*)(Wo2p + (kk + 1) * 512);
                uint32_t a0, a1, a2, a3;
                #pragma unroll
                for (int mt = 0; mt < 2; ++mt) {
                    LDSM4(a0, a1, a2, a3, AH(h1b, (2 * mh + mt), kk * 8));
                    MMA(acc2[mt][0], a0, a1, a2, a3, B0.x, B0.y);
                    MMA(acc2[mt][1], a0, a1, a2, a3, B0.z, B0.w);
                }
                B0 = nB0;
            }
        }
        #pragma unroll
        for (int mt = 0; mt < 2; ++mt)
            #pragma unroll
            for (int nt = 0; nt < 2; ++nt) {
                int n0 = wn * 16 + nt * 8 + 2 * t;
                int r0 = 32 * mh + 16 * mt + g, r1 = r0 + 8;
                smf[SMS_OFF + r0 * 68 + n0]     = tanhf(acc2[mt][nt][0]);
                smf[SMS_OFF + r0 * 68 + n0 + 1] = tanhf(acc2[mt][nt][1]);
                smf[SMS_OFF + r1 * 68 + n0]     = tanhf(acc2[mt][nt][2]);
                smf[SMS_OFF + r1 * 68 + n0 + 1] = tanhf(acc2[mt][nt][3]);
            }
        __syncthreads();   // [D]

        // ---- GEMM3 ----
        {
            const int row = tid >> 2, col = tid & 3;
            float a3 = smf[BFC_OFF + col];
            const float* mrow = &smf[SMS_OFF + row * 68];
            const float* wrow = &smf[WFC_OFF + col * 65];
            #pragma unroll 8
            for (int k = 0; k < DMID; ++k)
                a3 = fmaf(mrow[k], wrow[k], a3);
            outseq[((size_t)ts * B_SIZE + gbase + row) * DOUT + col] = a3;
        }
    }

    __syncthreads();
    // ---- h_final = H1 + H2 ----
    for (int i = tid; i < 64 * HKP; i += NTH) {
        int row = i >> 7, kp = i & 127;
        uint32_t w1 = H1[hidx(row, kp)], w2 = H2[hidx(row, kp)];
        float2 v;
        v.x = __bfloat162float(__ushort_as_bfloat16((unsigned short)(w1 & 0xFFFF))) +
              __bfloat162float(__ushort_as_bfloat16((unsigned short)(w2 & 0xFFFF)));
        v.y = __bfloat162float(__ushort_as_bfloat16((unsigned short)(w1 >> 16))) +
              __bfloat162float(__ushort_as_bfloat16((unsigned short)(w2 >> 16)));
        *(float2*)(hfin + (size_t)(gbase + row) * DH + kp * 2) = v;
    }
}

extern "C" void kernel_launch(void* const* d_in, const int* in_sizes, int n_in,
                              void* d_out, int out_size) {
    const float* x    = (const float*)d_in[0];
    const float* hc1  = (const float*)d_in[1];
    const float* Wi2h = (const float*)d_in[2];
    const float* bi2h = (const float*)d_in[3];
    const float* Wh2h = (const float*)d_in[4];
    const float* bh2h = (const float*)d_in[5];
    const float* Wh2o = (const float*)d_in[6];
    const float* bh2o = (const float*)d_in[7];
    const float* Wfc  = (const float*)d_in[8];
    const float* bfc  = (const float*)d_in[9];
    float* out = (float*)d_out;

    cudaFuncSetAttribute(rnn_kernel, cudaFuncAttributeMaxDynamicSharedMemorySize, SMEM_BYTES);

    prep_kernel<<<64, 256>>>(Wi2h, bi2h, Wh2h, bh2h, Wh2o);
    rnn_kernel<<<NCTAS, NTH, SMEM_BYTES>>>(x, hc1, Wfc, bh2o, bfc, out);
}